// round 14
// baseline (speedup 1.0000x reference)
#include <cuda_runtime.h>
#include <cuda_bf16.h>
#include <cstdint>
#include <math.h>

#define N_HALF 2048
#define NTOT   4096
#define D      512
#define TEMP_INV 10.0f   // 1/TEMPERATURE (also the exact sim upper bound)
#define GAMMA    0.5f    // 1/(2*SIGMA^2)

#define BM 128
#define BN 128
#define BK 64                     // bf16 per stage chunk (128B rows)
#define NCHUNK (D / BK)           // 8 K-chunks
#define NSTAGE 3

#define PREP_CTAS 148             // guaranteed wave-1 resident (2 CTA/SM, 148 SMs)
#define PREP_WARPS (PREP_CTAS * 8) // 1184

#define FP_SCALE 1099511627776.0  // 2^40 fixed-point scale (deterministic atomics)

// ---------------- scratch (static device memory; no allocations) ------------
__device__ __nv_bfloat16 g_U[(size_t)NTOT * D];       // normalized U, bf16
__device__ float g_invs[N_HALF];                      // 1 / (2*S[j'] - 1)
__device__ int   g_lab[N_HALF];
__device__ float g_pos[N_HALF];
__device__ unsigned long long g_accS[NTOT];
__device__ unsigned long long g_accA[NTOT];
__device__ unsigned long long g_accW[NTOT];
__device__ unsigned int g_prep_count;                 // zero-init; reset in k_final
__device__ unsigned int g_prep_flag;                  // zero-init; reset in k_final

// ---------------- helpers ----------------------------------------------------
__device__ __forceinline__ uint32_t smem_u32(const void* p) {
    uint32_t a;
    asm("{ .reg .u64 t; cvta.to.shared.u64 t, %1; cvt.u32.u64 %0, t; }"
        : "=r"(a) : "l"(p));
    return a;
}
__device__ __forceinline__ void cp16(uint32_t dst, const void* src) {
    asm volatile("cp.async.cg.shared.global [%0], [%1], 16;" :: "r"(dst), "l"(src));
}
#define CP_COMMIT() asm volatile("cp.async.commit_group;" ::: "memory")

__device__ __forceinline__ void ldsm4(uint32_t& r0, uint32_t& r1,
                                      uint32_t& r2, uint32_t& r3, uint32_t addr) {
    asm volatile("ldmatrix.sync.aligned.m8n8.x4.shared.b16 {%0,%1,%2,%3}, [%4];"
                 : "=r"(r0), "=r"(r1), "=r"(r2), "=r"(r3) : "r"(addr));
}
__device__ __forceinline__ void mma16816(float* c, const uint32_t* a,
                                         const uint32_t* b) {
    asm volatile(
        "mma.sync.aligned.m16n8k16.row.col.f32.bf16.bf16.f32 "
        "{%0,%1,%2,%3}, {%4,%5,%6,%7}, {%8,%9}, {%0,%1,%2,%3};\n"
        : "+f"(c[0]), "+f"(c[1]), "+f"(c[2]), "+f"(c[3])
        : "r"(a[0]), "r"(a[1]), "r"(a[2]), "r"(a[3]), "r"(b[0]), "r"(b[1]));
}
__device__ __forceinline__ void atomic_add_fx(unsigned long long* p, float v) {
    long long q = (long long)((double)v * FP_SCALE);
    atomicAdd(p, (unsigned long long)q);
}

// ---------------- K1: fused prep + symmetric Gram GEMM + row statistics -----
// CTAs 0..147 run the prep phase (norm -> bf16 U, colscale, acc zeroing) in
// a warp-strided partition, then release a global flag. All 528 CTAs wait on
// the flag before their tile. Prep CTAs are wave-1 resident => no deadlock.
extern __shared__ uint8_t dynsmem[];

__global__ __launch_bounds__(256, 2) void k_gemm_fused(
        const float* __restrict__ zi, const float* __restrict__ zj,
        const int* __restrict__ labraw, const float* __restrict__ zpos) {
    int tid = threadIdx.x;
    int warp = tid >> 5, lane = tid & 31;
    int g = lane >> 2, tq = lane & 3;
    int warpRow = (warp >> 2) * 64;
    int warpCol = (warp & 3) * 32;

    int b = blockIdx.x, by = 0;
    while (b >= 32 - by) { b -= 32 - by; ++by; }
    int bx = by + b;
    int rowBase = by * BM, colBase = bx * BN;
    bool diag = (bx == by);

    uint32_t raw = smem_u32(dynsmem);
    uint32_t base = (raw + 1023u) & ~1023u;
    uint32_t sa[NSTAGE], sb[NSTAGE];
    #pragma unroll
    for (int s = 0; s < NSTAGE; ++s) {
        sa[s] = base + s * 16384u;
        sb[s] = base + (NSTAGE + s) * 16384u;
    }
    uint8_t* ep = dynsmem + (base - raw);

    // ================= phase 0: prep (CTAs 0..147) =================
    if (blockIdx.x < PREP_CTAS) {
        float* sp = reinterpret_cast<float*>(ep);          // [2048]
        int*   sl = reinterpret_cast<int*>(sp + N_HALF);   // [2048]
        __shared__ int s_is64;
        if (tid == 0) s_is64 = 1;
        __syncthreads();
        for (int m = tid; m < N_HALF; m += 256)
            if (labraw[2 * m + 1] != 0) s_is64 = 0;
        for (int m = tid; m < N_HALF; m += 256) sp[m] = zpos[m];
        __syncthreads();
        int is64 = s_is64;
        for (int m = tid; m < N_HALF; m += 256)
            sl[m] = is64 ? labraw[2 * m] : labraw[m];
        __syncthreads();

        int gw = blockIdx.x * 8 + warp;          // 0..1183
        // ---- norm: warp-per-row, MLP=4, rows gw, gw+1184, ... ----
        for (int row = gw; row < NTOT; row += PREP_WARPS) {
            const float4* src = reinterpret_cast<const float4*>(
                (row < N_HALF) ? (zi + (size_t)row * D)
                               : (zj + (size_t)(row - N_HALF) * D));
            float4 v[4];
            #pragma unroll
            for (int q = 0; q < 4; ++q) v[q] = src[lane + q * 32];
            float ss = 0.f;
            #pragma unroll
            for (int q = 0; q < 4; ++q)
                ss += v[q].x * v[q].x + v[q].y * v[q].y
                    + v[q].z * v[q].z + v[q].w * v[q].w;
            #pragma unroll
            for (int o = 16; o > 0; o >>= 1)
                ss += __shfl_xor_sync(0xffffffffu, ss, o);
            float rinv = 1.f / fmaxf(sqrtf(ss), 1e-12f);
            #pragma unroll
            for (int q = 0; q < 4; ++q) {
                __nv_bfloat162 lo = __floats2bfloat162_rn(v[q].x * rinv, v[q].y * rinv);
                __nv_bfloat162 hi = __floats2bfloat162_rn(v[q].z * rinv, v[q].w * rinv);
                uint2 pk = make_uint2(*reinterpret_cast<uint32_t*>(&lo),
                                      *reinterpret_cast<uint32_t*>(&hi));
                *reinterpret_cast<uint2*>(
                    &g_U[(size_t)row * D + (lane + q * 32) * 4]) = pk;
            }
        }
        // ---- colscale: warp-per-j over smem tables ----
        for (int j = gw; j < N_HALF; j += PREP_WARPS) {
            int lj = sl[j]; float pj = sp[j];
            float acc = 0.f;
            #pragma unroll 4
            for (int m = lane; m < N_HALF; m += 32) {
                float d = sp[m] - pj;
                float k = __expf(-GAMMA * d * d);
                acc += (sl[m] == lj) ? k : 0.f;
            }
            #pragma unroll
            for (int o = 16; o > 0; o >>= 1)
                acc += __shfl_xor_sync(0xffffffffu, acc, o);
            if (lane == 0) {
                g_invs[j] = 1.f / (2.f * acc - 1.f);
                g_lab[j] = lj; g_pos[j] = pj;
            }
        }
        // ---- zero accumulators: 28 rows per CTA covers 4144 >= 4096 ----
        if (tid < 28) {
            int idx = blockIdx.x * 28 + tid;
            if (idx < NTOT) {
                g_accS[idx] = 0ull; g_accA[idx] = 0ull; g_accW[idx] = 0ull;
            }
        }
        __syncthreads();
        if (tid == 0) {
            __threadfence();
            unsigned int arrived = atomicAdd(&g_prep_count, 1u);
            if (arrived == PREP_CTAS - 1u) atomicExch(&g_prep_flag, 1u);
        }
    }

    // ================= barrier: all CTAs wait for prep =================
    if (tid == 0) {
        volatile unsigned int* vf = &g_prep_flag;
        while (*vf == 0u) __nanosleep(64);
    }
    __syncthreads();

    // ================= phase 1: GEMM mainloop (R7-identical) =================
    float* pR_s = reinterpret_cast<float*>(ep);            // [128]
    float* iR_s = pR_s + 128;
    int*   lR_s = reinterpret_cast<int*>(iR_s + 128);
    float* pC_s = reinterpret_cast<float*>(lR_s + 128);
    float* iC_s = pC_s + 128;
    int*   lC_s = reinterpret_cast<int*>(iC_s + 128);
    float* partR = reinterpret_cast<float*>(lC_s + 128);   // [8][64][3]
    float* partC = partR + 8 * 64 * 3;                     // [8][32][3]

    float acc[4][4][4];
    #pragma unroll
    for (int a = 0; a < 4; ++a)
        #pragma unroll
        for (int c = 0; c < 4; ++c)
            #pragma unroll
            for (int k = 0; k < 4; ++k) acc[a][c][k] = 0.f;

    const char* Ub = reinterpret_cast<const char*>(g_U);  // row stride 1024B

    int arow   = (lane & 7) + ((lane >> 3) & 1) * 8;
    int achsel = lane >> 4;
    int brow   = (lane & 7) + ((lane >> 4) << 3);
    int bchsel = (lane >> 3) & 1;
    int lxor   = lane & 7;

    #define LOAD_TILES(st, ck) do {                                            \
        uint32_t _sa = sa[st], _sb = sb[st];                                   \
        _Pragma("unroll")                                                      \
        for (int _i = 0; _i < 4; ++_i) {                                       \
            int _idx = _i * 256 + tid;                                         \
            int _row = _idx >> 3, _ch = _idx & 7;                              \
            uint32_t _sw = _row * 128 + ((_ch ^ (_row & 7)) << 4);             \
            cp16(_sa + _sw, Ub + (size_t)(rowBase + _row) * 1024 + (ck) * 128 + _ch * 16); \
            cp16(_sb + _sw, Ub + (size_t)(colBase + _row) * 1024 + (ck) * 128 + _ch * 16); \
        }                                                                      \
        CP_COMMIT();                                                           \
    } while (0)

    LOAD_TILES(0, 0);
    LOAD_TILES(1, 1);

    #pragma unroll
    for (int s = 0; s < NCHUNK; ++s) {
        int st = s % NSTAGE;
        if (s < NCHUNK - 1) asm volatile("cp.async.wait_group 1;" ::: "memory");
        else                asm volatile("cp.async.wait_group 0;" ::: "memory");
        __syncthreads();
        if (s + 2 < NCHUNK) {
            int st2 = (s + 2) % NSTAGE;
            LOAD_TILES(st2, s + 2);
        }

        uint32_t saSt = sa[st], sbSt = sb[st];
        #pragma unroll
        for (int kk = 0; kk < 4; ++kk) {
            uint32_t af[4][4], bf[4][2];
            #pragma unroll
            for (int mi = 0; mi < 4; ++mi) {
                uint32_t addr = saSt + (warpRow + mi * 16 + arow) * 128
                              + (((kk * 2 + achsel) ^ lxor) << 4);
                ldsm4(af[mi][0], af[mi][1], af[mi][2], af[mi][3], addr);
            }
            #pragma unroll
            for (int n2 = 0; n2 < 2; ++n2) {
                uint32_t addr = sbSt + (warpCol + n2 * 16 + brow) * 128
                              + (((kk * 2 + bchsel) ^ lxor) << 4);
                uint32_t r0, r1, r2, r3;
                ldsm4(r0, r1, r2, r3, addr);
                bf[n2 * 2][0] = r0;     bf[n2 * 2][1] = r1;
                bf[n2 * 2 + 1][0] = r2; bf[n2 * 2 + 1][1] = r3;
            }
            #pragma unroll
            for (int mi = 0; mi < 4; ++mi)
                #pragma unroll
                for (int ni = 0; ni < 4; ++ni)
                    mma16816(acc[mi][ni], af[mi], bf[ni]);
        }
    }
    #undef LOAD_TILES

    __syncthreads();

    // ================= fused epilogue =================
    if (tid < 128) {
        int r = (rowBase + tid) & (N_HALF - 1);
        int c = (colBase + tid) & (N_HALF - 1);
        pR_s[tid] = g_pos[r]; iR_s[tid] = g_invs[r]; lR_s[tid] = g_lab[r];
        pC_s[tid] = g_pos[c]; iC_s[tid] = g_invs[c]; lC_s[tid] = g_lab[c];
    }
    __syncthreads();

    float rS[8], rA[8], rW[8], cS[8], cA[8], cW[8];
    #pragma unroll
    for (int i = 0; i < 8; ++i) {
        rS[i] = rA[i] = rW[i] = 0.f;
        cS[i] = cA[i] = cW[i] = 0.f;
    }

    #pragma unroll
    for (int mi = 0; mi < 4; ++mi) {
        #pragma unroll
        for (int kh = 0; kh < 2; ++kh) {
            int rl = warpRow + mi * 16 + kh * 8 + g;
            float pr = pR_s[rl], ir = iR_s[rl];
            int   lr = lR_s[rl];
            int idxR = mi * 2 + kh;
            #pragma unroll
            for (int ni = 0; ni < 4; ++ni) {
                #pragma unroll
                for (int kb = 0; kb < 2; ++kb) {
                    int cl = warpCol + ni * 8 + tq * 2 + kb;
                    float sim = acc[mi][ni][kh * 2 + kb] * TEMP_INV;
                    float eS = __expf(sim - TEMP_INV);
                    float d  = pr - pC_s[cl];
                    float wk = (lr == lC_s[cl]) ? __expf(-GAMMA * d * d) : 0.f;
                    if (diag && rl == cl) { eS = 0.f; wk = 0.f; }
                    float wc = wk * iC_s[cl];
                    int idxC = ni * 2 + kb;
                    rS[idxR] += eS; rA[idxR] += sim * wc; rW[idxR] += wc;
                    float wr = wk * ir;
                    cS[idxC] += eS; cA[idxC] += sim * wr; cW[idxC] += wr;
                }
            }
        }
    }

    #pragma unroll
    for (int i = 0; i < 8; ++i) {
        rS[i] += __shfl_xor_sync(0xffffffffu, rS[i], 1);
        rS[i] += __shfl_xor_sync(0xffffffffu, rS[i], 2);
        rA[i] += __shfl_xor_sync(0xffffffffu, rA[i], 1);
        rA[i] += __shfl_xor_sync(0xffffffffu, rA[i], 2);
        rW[i] += __shfl_xor_sync(0xffffffffu, rW[i], 1);
        rW[i] += __shfl_xor_sync(0xffffffffu, rW[i], 2);
        cS[i] += __shfl_xor_sync(0xffffffffu, cS[i], 4);
        cS[i] += __shfl_xor_sync(0xffffffffu, cS[i], 8);
        cS[i] += __shfl_xor_sync(0xffffffffu, cS[i], 16);
        cA[i] += __shfl_xor_sync(0xffffffffu, cA[i], 4);
        cA[i] += __shfl_xor_sync(0xffffffffu, cA[i], 8);
        cA[i] += __shfl_xor_sync(0xffffffffu, cA[i], 16);
        cW[i] += __shfl_xor_sync(0xffffffffu, cW[i], 4);
        cW[i] += __shfl_xor_sync(0xffffffffu, cW[i], 8);
        cW[i] += __shfl_xor_sync(0xffffffffu, cW[i], 16);
    }
    if (tq == 0) {
        #pragma unroll
        for (int i = 0; i < 8; ++i) {
            int rl = (i >> 1) * 16 + (i & 1) * 8 + g;
            float* p = &partR[(warp * 64 + rl) * 3];
            p[0] = rS[i]; p[1] = rA[i]; p[2] = rW[i];
        }
    }
    if (g == 0) {
        #pragma unroll
        for (int i = 0; i < 8; ++i) {
            int cl = (i >> 1) * 8 + tq * 2 + (i & 1);
            float* p = &partC[(warp * 32 + cl) * 3];
            p[0] = cS[i]; p[1] = cA[i]; p[2] = cW[i];
        }
    }
    __syncthreads();

    if (tid < 128) {
        int wb = (tid >> 6) * 4;
        int lr2 = tid & 63;
        float S = 0.f, A = 0.f, W = 0.f;
        #pragma unroll
        for (int w = 0; w < 4; ++w) {
            const float* p = &partR[((wb + w) * 64 + lr2) * 3];
            S += p[0]; A += p[1]; W += p[2];
        }
        int grow = rowBase + tid;
        atomic_add_fx(&g_accS[grow], S);
        atomic_add_fx(&g_accA[grow], A);
        atomic_add_fx(&g_accW[grow], W);
    } else if (!diag) {
        int t2 = tid - 128;
        int grp = t2 >> 5, lc2 = t2 & 31;
        const float* p0 = &partC[(grp * 32 + lc2) * 3];
        const float* p1 = &partC[((grp + 4) * 32 + lc2) * 3];
        int gcol = colBase + t2;
        atomic_add_fx(&g_accS[gcol], p0[0] + p1[0]);
        atomic_add_fx(&g_accA[gcol], p0[1] + p1[1]);
        atomic_add_fx(&g_accW[gcol], p0[2] + p1[2]);
    }
}

// ---------------- K2: final per-row loss + reset prep barrier ---------------
__global__ void k_final(float* __restrict__ out) {
    int t = threadIdx.x;  // 1024
    const float inv_scale = (float)(1.0 / FP_SCALE);
    float a = 0.f;
    #pragma unroll
    for (int q = 0; q < 4; ++q) {
        int r = t + q * 1024;
        float S = (float)(long long)g_accS[r] * inv_scale;
        float A = (float)(long long)g_accA[r] * inv_scale;
        float W = (float)(long long)g_accW[r] * inv_scale;
        float lse = TEMP_INV + logf(S);
        a += A - lse * W;
    }
    #pragma unroll
    for (int o = 16; o > 0; o >>= 1) a += __shfl_xor_sync(0xffffffffu, a, o);
    __shared__ float sred[32];
    if ((t & 31) == 0) sred[t >> 5] = a;
    __syncthreads();
    if (t == 0) {
        float tot = 0.f;
        #pragma unroll
        for (int w = 0; w < 32; ++w) tot += sred[w];
        out[0] = -tot / (float)N_HALF;
        // reset prep barrier for the next graph replay
        g_prep_count = 0u;
        g_prep_flag = 0u;
    }
}

// ---------------- launch -----------------------------------------------------
extern "C" void kernel_launch(void* const* d_in, const int* in_sizes, int n_in,
                              void* d_out, int out_size) {
    const float* z_i   = (const float*)d_in[0];
    const float* z_j   = (const float*)d_in[1];
    const int*   labs  = (const int*)d_in[2];
    const float* z_pos = (const float*)d_in[3];
    float* out = (float*)d_out;

    const int dyn_smem = 99328;   // 6 x 16KB stage buffers + 1KB align slack
    cudaFuncSetAttribute(k_gemm_fused, cudaFuncAttributeMaxDynamicSharedMemorySize,
                         dyn_smem);

    k_gemm_fused<<<528, 256, dyn_smem>>>(z_i, z_j, labs, z_pos);
    k_final<<<1, 1024>>>(out);
}

// round 15
// speedup vs baseline: 1.0800x; 1.0800x over previous
#include <cuda_runtime.h>
#include <cuda_bf16.h>
#include <cstdint>
#include <math.h>

#define N_HALF 2048
#define NTOT   4096
#define D      512
#define TEMP_INV 10.0f   // 1/TEMPERATURE (also the exact sim upper bound)
#define GAMMA    0.5f    // 1/(2*SIGMA^2)

#define BM 128
#define BN 128
#define BK 64                     // bf16 per stage chunk (128B rows)
#define NCHUNK (D / BK)           // 8 K-chunks
#define NSTAGE 3

#define FP_SCALE 1099511627776.0  // 2^40 fixed-point scale (deterministic atomics)

// ---------------- scratch (static device memory; no allocations) ------------
__device__ __nv_bfloat16 g_U[(size_t)NTOT * D];       // normalized U, bf16
__device__ float g_invs[N_HALF];                      // 1 / (2*S[j'] - 1)
__device__ int   g_lab[N_HALF];
__device__ float g_pos[N_HALF];
__device__ unsigned long long g_accS[NTOT];
__device__ unsigned long long g_accA[NTOT];
__device__ unsigned long long g_accW[NTOT];

// ---------------- helpers ----------------------------------------------------
__device__ __forceinline__ uint32_t smem_u32(const void* p) {
    uint32_t a;
    asm("{ .reg .u64 t; cvta.to.shared.u64 t, %1; cvt.u32.u64 %0, t; }"
        : "=r"(a) : "l"(p));
    return a;
}
__device__ __forceinline__ void cp16(uint32_t dst, const void* src) {
    asm volatile("cp.async.cg.shared.global [%0], [%1], 16;" :: "r"(dst), "l"(src));
}
#define CP_COMMIT() asm volatile("cp.async.commit_group;" ::: "memory")

__device__ __forceinline__ void ldsm4(uint32_t& r0, uint32_t& r1,
                                      uint32_t& r2, uint32_t& r3, uint32_t addr) {
    asm volatile("ldmatrix.sync.aligned.m8n8.x4.shared.b16 {%0,%1,%2,%3}, [%4];"
                 : "=r"(r0), "=r"(r1), "=r"(r2), "=r"(r3) : "r"(addr));
}
__device__ __forceinline__ void mma16816(float* c, const uint32_t* a,
                                         const uint32_t* b) {
    asm volatile(
        "mma.sync.aligned.m16n8k16.row.col.f32.bf16.bf16.f32 "
        "{%0,%1,%2,%3}, {%4,%5,%6,%7}, {%8,%9}, {%0,%1,%2,%3};\n"
        : "+f"(c[0]), "+f"(c[1]), "+f"(c[2]), "+f"(c[3])
        : "r"(a[0]), "r"(a[1]), "r"(a[2]), "r"(a[3]), "r"(b[0]), "r"(b[1]));
}
__device__ __forceinline__ void atomic_add_fx(unsigned long long* p, float v) {
    long long q = (long long)((double)v * FP_SCALE);
    atomicAdd(p, (unsigned long long)q);
}

// ---------------- K1: prep. Blocks 0..255: colscale (FIRST, heavy).  --------
// Blocks 256..767: warp-per-row L2 normalization, MLP=4 (4 independent
// float4 loads per lane, pure warp-shfl reduction, no barriers).
__global__ __launch_bounds__(256) void k_prep(const float* __restrict__ zi,
                                              const float* __restrict__ zj,
                                              const int* __restrict__ labraw,
                                              const float* __restrict__ zpos) {
    int bb = blockIdx.x, t = threadIdx.x;
    if (bb < 256) {
        // ---- colscale: warp w owns j = bb*8 + w ----
        __shared__ float sp[N_HALF];
        __shared__ int   sl[N_HALF];
        __shared__ int   s_is64;
        int warp = t >> 5, lane = t & 31;
        if (t == 0) s_is64 = 1;
        __syncthreads();
        for (int m = t; m < N_HALF; m += 256)
            if (labraw[2 * m + 1] != 0) s_is64 = 0;
        for (int m = t; m < N_HALF; m += 256) sp[m] = zpos[m];
        __syncthreads();
        int is64 = s_is64;
        for (int m = t; m < N_HALF; m += 256)
            sl[m] = is64 ? labraw[2 * m] : labraw[m];
        __syncthreads();

        int j = bb * 8 + warp;          // 0..2047
        int lj = sl[j]; float pj = sp[j];
        float acc = 0.f;
        #pragma unroll 4
        for (int m = lane; m < N_HALF; m += 32) {
            float d = sp[m] - pj;
            float k = __expf(-GAMMA * d * d);
            acc += (sl[m] == lj) ? k : 0.f;
        }
        #pragma unroll
        for (int o = 16; o > 0; o >>= 1)
            acc += __shfl_xor_sync(0xffffffffu, acc, o);
        if (lane == 0) {
            g_invs[j] = 1.f / (2.f * acc - 1.f);
            g_lab[j] = lj; g_pos[j] = pj;
        }
        // zero 16 accumulator rows per block (4096/256)
        if (t < 16) {
            int idx = bb * 16 + t;
            g_accS[idx] = 0ull; g_accA[idx] = 0ull; g_accW[idx] = 0ull;
        }
    } else {
        // ---- warp-per-row normalization: row = (bb-256)*8 + warp ----
        int warp = t >> 5, lane = t & 31;
        int row = (bb - 256) * 8 + warp;
        const float4* src = reinterpret_cast<const float4*>(
            (row < N_HALF) ? (zi + (size_t)row * D)
                           : (zj + (size_t)(row - N_HALF) * D));
        float4 v[4];
        #pragma unroll
        for (int q = 0; q < 4; ++q) v[q] = src[lane + q * 32];  // MLP=4
        float ss = 0.f;
        #pragma unroll
        for (int q = 0; q < 4; ++q)
            ss += v[q].x * v[q].x + v[q].y * v[q].y
                + v[q].z * v[q].z + v[q].w * v[q].w;
        #pragma unroll
        for (int o = 16; o > 0; o >>= 1)
            ss += __shfl_xor_sync(0xffffffffu, ss, o);
        float rinv = 1.f / fmaxf(sqrtf(ss), 1e-12f);
        #pragma unroll
        for (int q = 0; q < 4; ++q) {
            __nv_bfloat162 lo = __floats2bfloat162_rn(v[q].x * rinv, v[q].y * rinv);
            __nv_bfloat162 hi = __floats2bfloat162_rn(v[q].z * rinv, v[q].w * rinv);
            uint2 pk = make_uint2(*reinterpret_cast<uint32_t*>(&lo),
                                  *reinterpret_cast<uint32_t*>(&hi));
            *reinterpret_cast<uint2*>(
                &g_U[(size_t)row * D + (lane + q * 32) * 4]) = pk;
        }
    }
}

// ---------------- K2: fused symmetric Gram GEMM + row statistics ------------
// Upper-triangular tiles (528 CTAs). 256 thr, 8 warps (2x4), warp tile 64x32,
// BK=64 bf16, 3-stage cp.async, fully unrolled, XOR-swizzled smem, ldmatrix.
// Epilogue: per-element softmax/weight stats for BOTH tile orientations,
// CTA-reduced, then deterministic fixed-point int64 atomics.
extern __shared__ uint8_t dynsmem[];

__global__ __launch_bounds__(256, 2) void k_gemm_fused() {
    int tid = threadIdx.x;
    int warp = tid >> 5, lane = tid & 31;
    int g = lane >> 2, tq = lane & 3;
    int warpRow = (warp >> 2) * 64;
    int warpCol = (warp & 3) * 32;

    int b = blockIdx.x, by = 0;
    while (b >= 32 - by) { b -= 32 - by; ++by; }
    int bx = by + b;
    int rowBase = by * BM, colBase = bx * BN;
    bool diag = (bx == by);

    uint32_t raw = smem_u32(dynsmem);
    uint32_t base = (raw + 1023u) & ~1023u;
    uint32_t sa[NSTAGE], sb[NSTAGE];
    #pragma unroll
    for (int s = 0; s < NSTAGE; ++s) {
        sa[s] = base + s * 16384u;
        sb[s] = base + (NSTAGE + s) * 16384u;
    }
    uint8_t* ep = dynsmem + (base - raw);
    float* pR_s = reinterpret_cast<float*>(ep);            // [128]
    float* iR_s = pR_s + 128;
    int*   lR_s = reinterpret_cast<int*>(iR_s + 128);
    float* pC_s = reinterpret_cast<float*>(lR_s + 128);
    float* iC_s = pC_s + 128;
    int*   lC_s = reinterpret_cast<int*>(iC_s + 128);
    float* partR = reinterpret_cast<float*>(lC_s + 128);   // [8][64][3]
    float* partC = partR + 8 * 64 * 3;                     // [8][32][3]

    float acc[4][4][4];
    #pragma unroll
    for (int a = 0; a < 4; ++a)
        #pragma unroll
        for (int c = 0; c < 4; ++c)
            #pragma unroll
            for (int k = 0; k < 4; ++k) acc[a][c][k] = 0.f;

    const char* Ub = reinterpret_cast<const char*>(g_U);  // row stride 1024B

    int arow   = (lane & 7) + ((lane >> 3) & 1) * 8;
    int achsel = lane >> 4;
    int brow   = (lane & 7) + ((lane >> 4) << 3);
    int bchsel = (lane >> 3) & 1;
    int lxor   = lane & 7;

    #define LOAD_TILES(st, ck) do {                                            \
        uint32_t _sa = sa[st], _sb = sb[st];                                   \
        _Pragma("unroll")                                                      \
        for (int _i = 0; _i < 4; ++_i) {                                       \
            int _idx = _i * 256 + tid;                                         \
            int _row = _idx >> 3, _ch = _idx & 7;                              \
            uint32_t _sw = _row * 128 + ((_ch ^ (_row & 7)) << 4);             \
            cp16(_sa + _sw, Ub + (size_t)(rowBase + _row) * 1024 + (ck) * 128 + _ch * 16); \
            cp16(_sb + _sw, Ub + (size_t)(colBase + _row) * 1024 + (ck) * 128 + _ch * 16); \
        }                                                                      \
        CP_COMMIT();                                                           \
    } while (0)

    LOAD_TILES(0, 0);
    LOAD_TILES(1, 1);

    #pragma unroll
    for (int s = 0; s < NCHUNK; ++s) {
        int st = s % NSTAGE;
        if (s < NCHUNK - 1) asm volatile("cp.async.wait_group 1;" ::: "memory");
        else                asm volatile("cp.async.wait_group 0;" ::: "memory");
        __syncthreads();
        if (s + 2 < NCHUNK) {
            int st2 = (s + 2) % NSTAGE;
            LOAD_TILES(st2, s + 2);
        }

        uint32_t saSt = sa[st], sbSt = sb[st];
        #pragma unroll
        for (int kk = 0; kk < 4; ++kk) {
            uint32_t af[4][4], bf[4][2];
            #pragma unroll
            for (int mi = 0; mi < 4; ++mi) {
                uint32_t addr = saSt + (warpRow + mi * 16 + arow) * 128
                              + (((kk * 2 + achsel) ^ lxor) << 4);
                ldsm4(af[mi][0], af[mi][1], af[mi][2], af[mi][3], addr);
            }
            #pragma unroll
            for (int n2 = 0; n2 < 2; ++n2) {
                uint32_t addr = sbSt + (warpCol + n2 * 16 + brow) * 128
                              + (((kk * 2 + bchsel) ^ lxor) << 4);
                uint32_t r0, r1, r2, r3;
                ldsm4(r0, r1, r2, r3, addr);
                bf[n2 * 2][0] = r0;     bf[n2 * 2][1] = r1;
                bf[n2 * 2 + 1][0] = r2; bf[n2 * 2 + 1][1] = r3;
            }
            #pragma unroll
            for (int mi = 0; mi < 4; ++mi)
                #pragma unroll
                for (int ni = 0; ni < 4; ++ni)
                    mma16816(acc[mi][ni], af[mi], bf[ni]);
        }
    }
    #undef LOAD_TILES

    __syncthreads();

    // ================= fused epilogue =================
    if (tid < 128) {
        int r = (rowBase + tid) & (N_HALF - 1);
        int c = (colBase + tid) & (N_HALF - 1);
        pR_s[tid] = g_pos[r]; iR_s[tid] = g_invs[r]; lR_s[tid] = g_lab[r];
        pC_s[tid] = g_pos[c]; iC_s[tid] = g_invs[c]; lC_s[tid] = g_lab[c];
    }
    __syncthreads();

    float rS[8], rA[8], rW[8], cS[8], cA[8], cW[8];
    #pragma unroll
    for (int i = 0; i < 8; ++i) {
        rS[i] = rA[i] = rW[i] = 0.f;
        cS[i] = cA[i] = cW[i] = 0.f;
    }

    #pragma unroll
    for (int mi = 0; mi < 4; ++mi) {
        #pragma unroll
        for (int kh = 0; kh < 2; ++kh) {
            int rl = warpRow + mi * 16 + kh * 8 + g;
            float pr = pR_s[rl], ir = iR_s[rl];
            int   lr = lR_s[rl];
            int idxR = mi * 2 + kh;
            #pragma unroll
            for (int ni = 0; ni < 4; ++ni) {
                #pragma unroll
                for (int kb = 0; kb < 2; ++kb) {
                    int cl = warpCol + ni * 8 + tq * 2 + kb;
                    float sim = acc[mi][ni][kh * 2 + kb] * TEMP_INV;
                    float eS = __expf(sim - TEMP_INV);
                    float d  = pr - pC_s[cl];
                    float wk = (lr == lC_s[cl]) ? __expf(-GAMMA * d * d) : 0.f;
                    if (diag && rl == cl) { eS = 0.f; wk = 0.f; }
                    float wc = wk * iC_s[cl];
                    int idxC = ni * 2 + kb;
                    rS[idxR] += eS; rA[idxR] += sim * wc; rW[idxR] += wc;
                    float wr = wk * ir;
                    cS[idxC] += eS; cA[idxC] += sim * wr; cW[idxC] += wr;
                }
            }
        }
    }

    #pragma unroll
    for (int i = 0; i < 8; ++i) {
        rS[i] += __shfl_xor_sync(0xffffffffu, rS[i], 1);
        rS[i] += __shfl_xor_sync(0xffffffffu, rS[i], 2);
        rA[i] += __shfl_xor_sync(0xffffffffu, rA[i], 1);
        rA[i] += __shfl_xor_sync(0xffffffffu, rA[i], 2);
        rW[i] += __shfl_xor_sync(0xffffffffu, rW[i], 1);
        rW[i] += __shfl_xor_sync(0xffffffffu, rW[i], 2);
        cS[i] += __shfl_xor_sync(0xffffffffu, cS[i], 4);
        cS[i] += __shfl_xor_sync(0xffffffffu, cS[i], 8);
        cS[i] += __shfl_xor_sync(0xffffffffu, cS[i], 16);
        cA[i] += __shfl_xor_sync(0xffffffffu, cA[i], 4);
        cA[i] += __shfl_xor_sync(0xffffffffu, cA[i], 8);
        cA[i] += __shfl_xor_sync(0xffffffffu, cA[i], 16);
        cW[i] += __shfl_xor_sync(0xffffffffu, cW[i], 4);
        cW[i] += __shfl_xor_sync(0xffffffffu, cW[i], 8);
        cW[i] += __shfl_xor_sync(0xffffffffu, cW[i], 16);
    }
    if (tq == 0) {
        #pragma unroll
        for (int i = 0; i < 8; ++i) {
            int rl = (i >> 1) * 16 + (i & 1) * 8 + g;
            float* p = &partR[(warp * 64 + rl) * 3];
            p[0] = rS[i]; p[1] = rA[i]; p[2] = rW[i];
        }
    }
    if (g == 0) {
        #pragma unroll
        for (int i = 0; i < 8; ++i) {
            int cl = (i >> 1) * 8 + tq * 2 + (i & 1);
            float* p = &partC[(warp * 32 + cl) * 3];
            p[0] = cS[i]; p[1] = cA[i]; p[2] = cW[i];
        }
    }
    __syncthreads();

    if (tid < 128) {
        int wb = (tid >> 6) * 4;
        int lr2 = tid & 63;
        float S = 0.f, A = 0.f, W = 0.f;
        #pragma unroll
        for (int w = 0; w < 4; ++w) {
            const float* p = &partR[((wb + w) * 64 + lr2) * 3];
            S += p[0]; A += p[1]; W += p[2];
        }
        int grow = rowBase + tid;
        atomic_add_fx(&g_accS[grow], S);
        atomic_add_fx(&g_accA[grow], A);
        atomic_add_fx(&g_accW[grow], W);
    } else if (!diag) {
        int t2 = tid - 128;
        int grp = t2 >> 5, lc2 = t2 & 31;
        const float* p0 = &partC[(grp * 32 + lc2) * 3];
        const float* p1 = &partC[((grp + 4) * 32 + lc2) * 3];
        int gcol = colBase + t2;
        atomic_add_fx(&g_accS[gcol], p0[0] + p1[0]);
        atomic_add_fx(&g_accA[gcol], p0[1] + p1[1]);
        atomic_add_fx(&g_accW[gcol], p0[2] + p1[2]);
    }
}

// ---------------- K3: final per-row loss (serial fp32, 1 block) -------------
__global__ void k_final(float* __restrict__ out) {
    int t = threadIdx.x;  // 1024
    const float inv_scale = (float)(1.0 / FP_SCALE);
    float a = 0.f;
    #pragma unroll
    for (int q = 0; q < 4; ++q) {
        int r = t + q * 1024;
        float S = (float)(long long)g_accS[r] * inv_scale;
        float A = (float)(long long)g_accA[r] * inv_scale;
        float W = (float)(long long)g_accW[r] * inv_scale;
        float lse = TEMP_INV + logf(S);
        a += A - lse * W;
    }
    #pragma unroll
    for (int o = 16; o > 0; o >>= 1) a += __shfl_xor_sync(0xffffffffu, a, o);
    __shared__ float sred[32];
    if ((t & 31) == 0) sred[t >> 5] = a;
    __syncthreads();
    if (t == 0) {
        float tot = 0.f;
        #pragma unroll
        for (int w = 0; w < 32; ++w) tot += sred[w];
        out[0] = -tot / (float)N_HALF;
    }
}

// ---------------- launch -----------------------------------------------------
extern "C" void kernel_launch(void* const* d_in, const int* in_sizes, int n_in,
                              void* d_out, int out_size) {
    const float* z_i   = (const float*)d_in[0];
    const float* z_j   = (const float*)d_in[1];
    const int*   labs  = (const int*)d_in[2];
    const float* z_pos = (const float*)d_in[3];
    float* out = (float*)d_out;

    const int dyn_smem = 99328;   // 6 x 16KB stage buffers + 1KB align slack
    cudaFuncSetAttribute(k_gemm_fused, cudaFuncAttributeMaxDynamicSharedMemorySize,
                         dyn_smem);

    k_prep<<<256 + 512, 256>>>(z_i, z_j, labs, z_pos);
    k_gemm_fused<<<528, 256, dyn_smem>>>();
    k_final<<<1, 1024>>>(out);
}